// round 4
// baseline (speedup 1.0000x reference)
#include <cuda_runtime.h>
#include <math.h>

// Problem constants
#define EXPERTS 8
#define HID     2048
#define IEXP    1408
#define SIEXP   2816
#define TTOK    4096
#define NPAIR   8192      // TTOK * top_k

#define BK 16
#define ASTR 132          // 128 + 4 padding

// ---------------- scratch ----------------
__device__ int   g_cnt[EXPERTS];
__device__ int   g_tok[EXPERTS * NPAIR];
__device__ int   g_pid[EXPERTS * NPAIR];
__device__ float g_pw [EXPERTS * NPAIR];
// act buffer: shared phase [TTOK][SIEXP], then routed phase [NPAIR][IEXP] (same size)
__device__ float g_act[11534336];
__device__ float g_pairout[NPAIR * HID];

__device__ __forceinline__ float silu_f(float a) { return a / (1.0f + expf(-a)); }

// ---------------- routing (verbatim R1) ----------------
__global__ void zero_cnt_kernel() {
    if (threadIdx.x < EXPERTS) g_cnt[threadIdx.x] = 0;
}

__global__ void route_kernel(const int* __restrict__ topk_idx,
                             const float* __restrict__ topk_w) {
    int p = blockIdx.x * blockDim.x + threadIdx.x;
    if (p < NPAIR) {
        int e = topk_idx[p];
        int pos = atomicAdd(&g_cnt[e], 1);
        g_tok[e * NPAIR + pos] = p >> 1;
        g_pid[e * NPAIR + pos] = p;
        g_pw [e * NPAIR + pos] = topk_w[p];
    }
}

// ---------------- shared GEMM1: 128 rows x 64 cols (both swiglu halves) ----------------
__global__ __launch_bounds__(256) void sgemm1_kernel(const float* __restrict__ X,
                                                     const float* __restrict__ W) {
    __shared__ float As[BK][ASTR];
    __shared__ float Ba[BK][64];
    __shared__ float Bb[BK][64];
    const int tid = threadIdx.x;
    const int tx = tid & 15, ty = tid >> 4;
    const int n0 = blockIdx.x * 64;
    const int m0 = blockIdx.y * 128;
    const int ldw = 2 * SIEXP;

    float accA[8][4] = {{0.f}}, accB[8][4] = {{0.f}};

    for (int k0 = 0; k0 < HID; k0 += BK) {
        #pragma unroll
        for (int h = 0; h < 2; h++) {
            int ar = h * 64 + (tid >> 2), ac = (tid & 3) << 2;
            float4 av = *(const float4*)&X[(size_t)(m0 + ar) * HID + k0 + ac];
            As[ac + 0][ar] = av.x; As[ac + 1][ar] = av.y;
            As[ac + 2][ar] = av.z; As[ac + 3][ar] = av.w;
        }
        {
            int kr = tid >> 4, nc = (tid & 15) << 2;
            *(float4*)&Ba[kr][nc] = *(const float4*)&W[(size_t)(k0 + kr) * ldw + n0 + nc];
            *(float4*)&Bb[kr][nc] = *(const float4*)&W[(size_t)(k0 + kr) * ldw + SIEXP + n0 + nc];
        }
        __syncthreads();
        #pragma unroll
        for (int kk = 0; kk < BK; kk++) {
            float4 a0 = *(const float4*)&As[kk][ty << 2];
            float4 a1 = *(const float4*)&As[kk][64 + (ty << 2)];
            float4 ba = *(const float4*)&Ba[kk][tx << 2];
            float4 bb = *(const float4*)&Bb[kk][tx << 2];
            float av[8]  = {a0.x, a0.y, a0.z, a0.w, a1.x, a1.y, a1.z, a1.w};
            float bav[4] = {ba.x, ba.y, ba.z, ba.w};
            float bbv[4] = {bb.x, bb.y, bb.z, bb.w};
            #pragma unroll
            for (int i = 0; i < 8; i++)
                #pragma unroll
                for (int j = 0; j < 4; j++) {
                    accA[i][j] = fmaf(av[i], bav[j], accA[i][j]);
                    accB[i][j] = fmaf(av[i], bbv[j], accB[i][j]);
                }
        }
        __syncthreads();
    }
    #pragma unroll
    for (int i = 0; i < 8; i++) {
        int lm = (i < 4) ? ((ty << 2) + i) : (64 + (ty << 2) + (i - 4));
        int row = m0 + lm;
        #pragma unroll
        for (int j = 0; j < 4; j++) {
            int col = n0 + (tx << 2) + j;
            g_act[(size_t)row * SIEXP + col] = silu_f(accA[i][j]) * accB[i][j];
        }
    }
}

// ---------------- shared GEMM2: 128x128 ----------------
__global__ __launch_bounds__(256) void sgemm2_kernel(const float* __restrict__ W,
                                                     float* __restrict__ out) {
    __shared__ float As[BK][ASTR];
    __shared__ float Bs[BK][128];
    const int tid = threadIdx.x;
    const int tx = tid & 15, ty = tid >> 4;
    const int n0 = blockIdx.x * 128;
    const int m0 = blockIdx.y * 128;

    float acc[8][8] = {{0.f}};

    for (int k0 = 0; k0 < SIEXP; k0 += BK) {
        #pragma unroll
        for (int h = 0; h < 2; h++) {
            int ar = h * 64 + (tid >> 2), ac = (tid & 3) << 2;
            float4 av = *(const float4*)&g_act[(size_t)(m0 + ar) * SIEXP + k0 + ac];
            As[ac + 0][ar] = av.x; As[ac + 1][ar] = av.y;
            As[ac + 2][ar] = av.z; As[ac + 3][ar] = av.w;
        }
        #pragma unroll
        for (int h = 0; h < 2; h++) {
            int kr = tid >> 4, nc = h * 64 + ((tid & 15) << 2);
            *(float4*)&Bs[kr][nc] = *(const float4*)&W[(size_t)(k0 + kr) * HID + n0 + nc];
        }
        __syncthreads();
        #pragma unroll
        for (int kk = 0; kk < BK; kk++) {
            float4 a0 = *(const float4*)&As[kk][ty << 2];
            float4 a1 = *(const float4*)&As[kk][64 + (ty << 2)];
            float4 b0 = *(const float4*)&Bs[kk][tx << 2];
            float4 b1 = *(const float4*)&Bs[kk][64 + (tx << 2)];
            float av[8] = {a0.x, a0.y, a0.z, a0.w, a1.x, a1.y, a1.z, a1.w};
            float bv[8] = {b0.x, b0.y, b0.z, b0.w, b1.x, b1.y, b1.z, b1.w};
            #pragma unroll
            for (int i = 0; i < 8; i++)
                #pragma unroll
                for (int j = 0; j < 8; j++)
                    acc[i][j] = fmaf(av[i], bv[j], acc[i][j]);
        }
        __syncthreads();
    }
    #pragma unroll
    for (int i = 0; i < 8; i++) {
        int lm = (i < 4) ? ((ty << 2) + i) : (64 + (ty << 2) + (i - 4));
        int row = m0 + lm;
        #pragma unroll
        for (int jh = 0; jh < 2; jh++) {
            int col = n0 + jh * 64 + (tx << 2);
            float4 v;
            v.x = acc[i][jh * 4 + 0]; v.y = acc[i][jh * 4 + 1];
            v.z = acc[i][jh * 4 + 2]; v.w = acc[i][jh * 4 + 3];
            *(float4*)&out[(size_t)row * HID + col] = v;
        }
    }
}

// ---------------- routed GEMM1: gather tokens, swiglu, scatter act by pid ----------------
__global__ __launch_bounds__(256) void rgemm1_kernel(const float* __restrict__ X,
                                                     const float* __restrict__ W1) {
    const int e = blockIdx.z;
    const int cnt = g_cnt[e];
    const int m0 = blockIdx.y * 128;
    if (m0 >= cnt) return;

    __shared__ float As[BK][ASTR];
    __shared__ float Ba[BK][64];
    __shared__ float Bb[BK][64];
    __shared__ int toks[128];
    __shared__ int pids[128];

    const int tid = threadIdx.x;
    const int tx = tid & 15, ty = tid >> 4;
    const int n0 = blockIdx.x * 64;
    const int ldw = 2 * IEXP;
    const float* W = W1 + (size_t)e * HID * (2 * IEXP);

    if (tid < 128) {
        int r = m0 + tid;
        bool ok = (r < cnt);
        toks[tid] = ok ? g_tok[e * NPAIR + r] : 0;
        pids[tid] = ok ? g_pid[e * NPAIR + r] : -1;
    }
    __syncthreads();

    float accA[8][4] = {{0.f}}, accB[8][4] = {{0.f}};

    for (int k0 = 0; k0 < HID; k0 += BK) {
        #pragma unroll
        for (int h = 0; h < 2; h++) {
            int ar = h * 64 + (tid >> 2), ac = (tid & 3) << 2;
            float4 av = *(const float4*)&X[(size_t)toks[ar] * HID + k0 + ac];
            As[ac + 0][ar] = av.x; As[ac + 1][ar] = av.y;
            As[ac + 2][ar] = av.z; As[ac + 3][ar] = av.w;
        }
        {
            int kr = tid >> 4, nc = (tid & 15) << 2;
            *(float4*)&Ba[kr][nc] = *(const float4*)&W[(size_t)(k0 + kr) * ldw + n0 + nc];
            *(float4*)&Bb[kr][nc] = *(const float4*)&W[(size_t)(k0 + kr) * ldw + IEXP + n0 + nc];
        }
        __syncthreads();
        #pragma unroll
        for (int kk = 0; kk < BK; kk++) {
            float4 a0 = *(const float4*)&As[kk][ty << 2];
            float4 a1 = *(const float4*)&As[kk][64 + (ty << 2)];
            float4 ba = *(const float4*)&Ba[kk][tx << 2];
            float4 bb = *(const float4*)&Bb[kk][tx << 2];
            float av[8]  = {a0.x, a0.y, a0.z, a0.w, a1.x, a1.y, a1.z, a1.w};
            float bav[4] = {ba.x, ba.y, ba.z, ba.w};
            float bbv[4] = {bb.x, bb.y, bb.z, bb.w};
            #pragma unroll
            for (int i = 0; i < 8; i++)
                #pragma unroll
                for (int j = 0; j < 4; j++) {
                    accA[i][j] = fmaf(av[i], bav[j], accA[i][j]);
                    accB[i][j] = fmaf(av[i], bbv[j], accB[i][j]);
                }
        }
        __syncthreads();
    }
    #pragma unroll
    for (int i = 0; i < 8; i++) {
        int lm = (i < 4) ? ((ty << 2) + i) : (64 + (ty << 2) + (i - 4));
        int pid = pids[lm];
        if (pid >= 0) {
            #pragma unroll
            for (int j = 0; j < 4; j++) {
                int col = n0 + (tx << 2) + j;
                g_act[(size_t)pid * IEXP + col] = silu_f(accA[i][j]) * accB[i][j];
            }
        }
    }
}

// ---------------- routed GEMM2: act[pid] @ W2[e], scaled, to pairout ----------------
__global__ __launch_bounds__(256) void rgemm2_kernel(const float* __restrict__ W2) {
    const int e = blockIdx.z;
    const int cnt = g_cnt[e];
    const int m0 = blockIdx.y * 128;
    if (m0 >= cnt) return;

    __shared__ float As[BK][ASTR];
    __shared__ float Bs[BK][128];
    __shared__ int   pids[128];
    __shared__ float ws[128];

    const int tid = threadIdx.x;
    const int tx = tid & 15, ty = tid >> 4;
    const int n0 = blockIdx.x * 128;
    const float* W = W2 + (size_t)e * IEXP * HID;

    if (tid < 128) {
        int r = m0 + tid;
        bool ok = (r < cnt);
        pids[tid] = ok ? g_pid[e * NPAIR + r] : -1;
        ws[tid]   = ok ? g_pw [e * NPAIR + r] : 0.f;
    }
    __syncthreads();

    float acc[8][8] = {{0.f}};

    for (int k0 = 0; k0 < IEXP; k0 += BK) {
        #pragma unroll
        for (int h = 0; h < 2; h++) {
            int ar = h * 64 + (tid >> 2), ac = (tid & 3) << 2;
            int src = pids[ar] >= 0 ? pids[ar] : 0;
            float4 av = *(const float4*)&g_act[(size_t)src * IEXP + k0 + ac];
            As[ac + 0][ar] = av.x; As[ac + 1][ar] = av.y;
            As[ac + 2][ar] = av.z; As[ac + 3][ar] = av.w;
        }
        #pragma unroll
        for (int h = 0; h < 2; h++) {
            int kr = tid >> 4, nc = h * 64 + ((tid & 15) << 2);
            *(float4*)&Bs[kr][nc] = *(const float4*)&W[(size_t)(k0 + kr) * HID + n0 + nc];
        }
        __syncthreads();
        #pragma unroll
        for (int kk = 0; kk < BK; kk++) {
            float4 a0 = *(const float4*)&As[kk][ty << 2];
            float4 a1 = *(const float4*)&As[kk][64 + (ty << 2)];
            float4 b0 = *(const float4*)&Bs[kk][tx << 2];
            float4 b1 = *(const float4*)&Bs[kk][64 + (tx << 2)];
            float av[8] = {a0.x, a0.y, a0.z, a0.w, a1.x, a1.y, a1.z, a1.w};
            float bv[8] = {b0.x, b0.y, b0.z, b0.w, b1.x, b1.y, b1.z, b1.w};
            #pragma unroll
            for (int i = 0; i < 8; i++)
                #pragma unroll
                for (int j = 0; j < 8; j++)
                    acc[i][j] = fmaf(av[i], bv[j], acc[i][j]);
        }
        __syncthreads();
    }
    #pragma unroll
    for (int i = 0; i < 8; i++) {
        int lm = (i < 4) ? ((ty << 2) + i) : (64 + (ty << 2) + (i - 4));
        int pid = pids[lm];
        if (pid >= 0) {
            float w = ws[lm];
            #pragma unroll
            for (int jh = 0; jh < 2; jh++) {
                int col = n0 + jh * 64 + (tx << 2);
                float4 v;
                v.x = w * acc[i][jh * 4 + 0]; v.y = w * acc[i][jh * 4 + 1];
                v.z = w * acc[i][jh * 4 + 2]; v.w = w * acc[i][jh * 4 + 3];
                *(float4*)&g_pairout[(size_t)pid * HID + col] = v;
            }
        }
    }
}

// ---------------- combine (verbatim R1) ----------------
__global__ void combine_kernel(float* __restrict__ out) {
    int v = blockIdx.x * blockDim.x + threadIdx.x;
    const int HV = HID / 4;
    if (v < TTOK * HV) {
        int t = v / HV;
        int h4 = v - t * HV;
        float4 o  = ((float4*)out)[v];
        float4 p0 = ((const float4*)g_pairout)[(size_t)(2 * t) * HV + h4];
        float4 p1 = ((const float4*)g_pairout)[(size_t)(2 * t + 1) * HV + h4];
        o.x += p0.x + p1.x; o.y += p0.y + p1.y;
        o.z += p0.z + p1.z; o.w += p0.w + p1.w;
        ((float4*)out)[v] = o;
    }
}

// ---------------- launcher ----------------
extern "C" void kernel_launch(void* const* d_in, const int* in_sizes, int n_in,
                              void* d_out, int out_size) {
    const float* x        = (const float*)d_in[0];  // [T, H]
    const float* topk_w   = (const float*)d_in[1];  // [T, 2]
    const float* W1       = (const float*)d_in[2];  // [E, H, 2I]
    const float* W2       = (const float*)d_in[3];  // [E, I, H]
    const float* Ws1      = (const float*)d_in[4];  // [H, 2SI]
    const float* Ws2      = (const float*)d_in[5];  // [SI, H]
    const int*   topk_idx = (const int*)d_in[6];    // [T, 2]
    float* out = (float*)d_out;                     // [T, H]

    (void)in_sizes; (void)n_in; (void)out_size;

    // routing
    zero_cnt_kernel<<<1, 32>>>();
    route_kernel<<<NPAIR / 256, 256>>>(topk_idx, topk_w);

    // shared expert path
    sgemm1_kernel<<<dim3(SIEXP / 64, TTOK / 128), 256>>>(x, Ws1);
    sgemm2_kernel<<<dim3(HID / 128, TTOK / 128), 256>>>(Ws2, out);

    // routed expert path (g_act reused after sgemm2 consumed it)
    rgemm1_kernel<<<dim3(IEXP / 64, NPAIR / 128, EXPERTS), 256>>>(x, W1);
    rgemm2_kernel<<<dim3(HID / 128, NPAIR / 128, EXPERTS), 256>>>(W2);

    // deterministic combine
    combine_kernel<<<(TTOK * (HID / 4) + 255) / 256, 256>>>(out);
}

// round 6
// speedup vs baseline: 4.0644x; 4.0644x over previous
#include <cuda_runtime.h>
#include <math.h>
#include <stdint.h>

#define EXPERTS 8
#define HID     2048
#define IEXP    1408
#define SIEXP   2816
#define TTOK    4096
#define NPAIR   8192

// ---------------- scratch ----------------
__device__ int   g_cnt[EXPERTS];
__device__ int   g_tok[EXPERTS * NPAIR];
__device__ int   g_pid[EXPERTS * NPAIR];
__device__ float g_pw [EXPERTS * NPAIR];
__device__ float g_act[11534336];        // [TTOK][SIEXP] then [NPAIR][IEXP]
__device__ float g_pairout[NPAIR * HID];

__device__ __forceinline__ float silu_f(float a) { return a / (1.0f + expf(-a)); }

__device__ __forceinline__ uint32_t f2t(float x) {
    uint32_t r; asm("cvt.rna.tf32.f32 %0, %1;" : "=r"(r) : "f"(x)); return r;
}

__device__ __forceinline__ void mma8(float& d0, float& d1, float& d2, float& d3,
                                     uint32_t a0, uint32_t a1, uint32_t a2, uint32_t a3,
                                     uint32_t b0, uint32_t b1) {
    asm volatile(
        "mma.sync.aligned.m16n8k8.row.col.f32.tf32.tf32.f32 "
        "{%0,%1,%2,%3},{%4,%5,%6,%7},{%8,%9},{%0,%1,%2,%3};"
        : "+f"(d0), "+f"(d1), "+f"(d2), "+f"(d3)
        : "r"(a0), "r"(a1), "r"(a2), "r"(a3), "r"(b0), "r"(b1));
}

// ---------------- routing ----------------
__global__ void zero_cnt_kernel() {
    if (threadIdx.x < EXPERTS) g_cnt[threadIdx.x] = 0;
}

__global__ void route_kernel(const int* __restrict__ topk_idx,
                             const float* __restrict__ topk_w) {
    int p = blockIdx.x * blockDim.x + threadIdx.x;
    if (p < NPAIR) {
        int e = topk_idx[p];
        int pos = atomicAdd(&g_cnt[e], 1);
        g_tok[e * NPAIR + pos] = p >> 1;
        g_pid[e * NPAIR + pos] = p;
        g_pw [e * NPAIR + pos] = topk_w[p];
    }
}

// =====================================================================
// GEMM1: h = silu(A @ Wg) * (A @ Wu), A rows gathered (routed) or direct.
// CTA: 128 rows x 64 h-cols. 8 warps = 4(M) x 2(N). Warp: 32x32 per half.
// =====================================================================
template<int ROUTED>
__global__ __launch_bounds__(256) void gemm1_tpl(const float* __restrict__ X,
                                                 const float* __restrict__ Wfull) {
    const int IN  = ROUTED ? IEXP : SIEXP;
    const int ldw = 2 * IN;
    const int K   = HID;
    const int m0 = blockIdx.y * 128;
    const int n0 = blockIdx.x * 64;

    __shared__ uint32_t As[128][36];
    __shared__ uint32_t Ba[32][72];
    __shared__ uint32_t Bb[32][72];
    __shared__ int s_tok[128];
    __shared__ int s_pid[128];

    const int tid = threadIdx.x;
    const float* W = Wfull;
    if (ROUTED) {
        const int e = blockIdx.z;
        const int cnt = g_cnt[e];
        if (m0 >= cnt) return;
        W += (size_t)e * HID * ldw;
        if (tid < 128) {
            int r = m0 + tid;
            bool ok = r < cnt;
            s_tok[tid] = ok ? g_tok[e * NPAIR + r] : 0;
            s_pid[tid] = ok ? g_pid[e * NPAIR + r] : -1;
        }
        __syncthreads();
    }

    const int lane = tid & 31, w = tid >> 5;
    const int gid = lane >> 2, tig = lane & 3;
    const int wm = w & 3, wn = w >> 2;

    int a_m[4], a_k[4];
    #pragma unroll
    for (int p = 0; p < 4; p++) {
        int idx = p * 256 + tid;
        int m = idx >> 3;
        a_m[p] = ROUTED ? s_tok[m] : (m0 + m);
        a_k[p] = (idx & 7) << 2;
    }

    float accA[2][4][4] = {}, accB[2][4][4] = {};

    float4 ra[4], rga[2], rgb[2];
    #pragma unroll
    for (int p = 0; p < 4; p++)
        ra[p] = *(const float4*)&X[(size_t)a_m[p] * HID + a_k[p]];
    #pragma unroll
    for (int p = 0; p < 2; p++) {
        int idx = p * 256 + tid;
        int kr = idx >> 4, nc = (idx & 15) << 2;
        rga[p] = *(const float4*)&W[(size_t)kr * ldw + n0 + nc];
        rgb[p] = *(const float4*)&W[(size_t)kr * ldw + IN + n0 + nc];
    }

    for (int k0 = 0; k0 < K; k0 += 32) {
        #pragma unroll
        for (int p = 0; p < 4; p++) {
            int idx = p * 256 + tid;
            int m = idx >> 3, k4 = (idx & 7) << 2;
            As[m][k4 + 0] = f2t(ra[p].x); As[m][k4 + 1] = f2t(ra[p].y);
            As[m][k4 + 2] = f2t(ra[p].z); As[m][k4 + 3] = f2t(ra[p].w);
        }
        #pragma unroll
        for (int p = 0; p < 2; p++) {
            int idx = p * 256 + tid;
            int kr = idx >> 4, nc = (idx & 15) << 2;
            Ba[kr][nc + 0] = f2t(rga[p].x); Ba[kr][nc + 1] = f2t(rga[p].y);
            Ba[kr][nc + 2] = f2t(rga[p].z); Ba[kr][nc + 3] = f2t(rga[p].w);
            Bb[kr][nc + 0] = f2t(rgb[p].x); Bb[kr][nc + 1] = f2t(rgb[p].y);
            Bb[kr][nc + 2] = f2t(rgb[p].z); Bb[kr][nc + 3] = f2t(rgb[p].w);
        }
        __syncthreads();

        if (k0 + 32 < K) {
            #pragma unroll
            for (int p = 0; p < 4; p++)
                ra[p] = *(const float4*)&X[(size_t)a_m[p] * HID + k0 + 32 + a_k[p]];
            #pragma unroll
            for (int p = 0; p < 2; p++) {
                int idx = p * 256 + tid;
                int kr = idx >> 4, nc = (idx & 15) << 2;
                rga[p] = *(const float4*)&W[(size_t)(k0 + 32 + kr) * ldw + n0 + nc];
                rgb[p] = *(const float4*)&W[(size_t)(k0 + 32 + kr) * ldw + IN + n0 + nc];
            }
        }

        #pragma unroll
        for (int ks = 0; ks < 4; ks++) {
            const int kk = ks * 8;
            uint32_t af[2][4];
            #pragma unroll
            for (int mt = 0; mt < 2; mt++) {
                int mr = wm * 32 + mt * 16;
                af[mt][0] = As[mr + gid    ][kk + tig];
                af[mt][1] = As[mr + gid + 8][kk + tig];
                af[mt][2] = As[mr + gid    ][kk + tig + 4];
                af[mt][3] = As[mr + gid + 8][kk + tig + 4];
            }
            #pragma unroll
            for (int nt = 0; nt < 4; nt++) {
                int nb = wn * 32 + nt * 8 + gid;
                uint32_t ba0 = Ba[kk + tig][nb], ba1 = Ba[kk + tig + 4][nb];
                uint32_t bb0 = Bb[kk + tig][nb], bb1 = Bb[kk + tig + 4][nb];
                #pragma unroll
                for (int mt = 0; mt < 2; mt++) {
                    mma8(accA[mt][nt][0], accA[mt][nt][1], accA[mt][nt][2], accA[mt][nt][3],
                         af[mt][0], af[mt][1], af[mt][2], af[mt][3], ba0, ba1);
                    mma8(accB[mt][nt][0], accB[mt][nt][1], accB[mt][nt][2], accB[mt][nt][3],
                         af[mt][0], af[mt][1], af[mt][2], af[mt][3], bb0, bb1);
                }
            }
        }
        __syncthreads();
    }

    // epilogue: swiglu, write g_act (device symbol, in-kernel reference)
    #pragma unroll
    for (int mt = 0; mt < 2; mt++) {
        int lm0 = wm * 32 + mt * 16 + gid;
        int lm1 = lm0 + 8;
        int row0, row1;
        if (ROUTED) { row0 = s_pid[lm0]; row1 = s_pid[lm1]; }
        else        { row0 = m0 + lm0;   row1 = m0 + lm1; }
        #pragma unroll
        for (int nt = 0; nt < 4; nt++) {
            int col = n0 + wn * 32 + nt * 8 + 2 * tig;
            if (row0 >= 0) {
                float2 v;
                v.x = silu_f(accA[mt][nt][0]) * accB[mt][nt][0];
                v.y = silu_f(accA[mt][nt][1]) * accB[mt][nt][1];
                *(float2*)&g_act[(size_t)row0 * IN + col] = v;
            }
            if (row1 >= 0) {
                float2 v;
                v.x = silu_f(accA[mt][nt][2]) * accB[mt][nt][2];
                v.y = silu_f(accA[mt][nt][3]) * accB[mt][nt][3];
                *(float2*)&g_act[(size_t)row1 * IN + col] = v;
            }
        }
    }
}

// =====================================================================
// GEMM2: C = act @ W (+ optional per-row scale, scatter by pid).
// CTA: 128 x 128. 8 warps = 2(M) x 4(N). Warp: 64x32.
// ROUTED=1 writes to device symbol g_pairout (NOT the C argument — device
// symbols must never be passed as kernel args from host).
// =====================================================================
template<int ROUTED>
__global__ __launch_bounds__(256) void gemm2_tpl(const float* __restrict__ Wfull,
                                                 float* __restrict__ C) {
    const int IN = ROUTED ? IEXP : SIEXP;   // K dim
    const int m0 = blockIdx.y * 128;
    const int n0 = blockIdx.x * 128;

    __shared__ uint32_t As[128][36];
    __shared__ uint32_t Bs[32][136];
    __shared__ int   s_pid[128];
    __shared__ float s_w[128];

    const int tid = threadIdx.x;
    const float* W = Wfull;
    float* Cw = ROUTED ? g_pairout : C;     // device-side symbol resolution
    if (ROUTED) {
        const int e = blockIdx.z;
        const int cnt = g_cnt[e];
        if (m0 >= cnt) return;
        W += (size_t)e * IEXP * HID;
        if (tid < 128) {
            int r = m0 + tid;
            bool ok = r < cnt;
            s_pid[tid] = ok ? g_pid[e * NPAIR + r] : -1;
            s_w[tid]   = ok ? g_pw [e * NPAIR + r] : 0.f;
        }
        __syncthreads();
    }

    const int lane = tid & 31, w = tid >> 5;
    const int gid = lane >> 2, tig = lane & 3;
    const int wm = w & 1, wn = w >> 1;

    int a_m[4], a_k[4];
    #pragma unroll
    for (int p = 0; p < 4; p++) {
        int idx = p * 256 + tid;
        int m = idx >> 3;
        int src = ROUTED ? (s_pid[m] >= 0 ? s_pid[m] : 0) : (m0 + m);
        a_m[p] = src;
        a_k[p] = (idx & 7) << 2;
    }

    float acc[4][4][4] = {};

    float4 ra[4], rb[4];
    #pragma unroll
    for (int p = 0; p < 4; p++)
        ra[p] = *(const float4*)&g_act[(size_t)a_m[p] * IN + a_k[p]];
    #pragma unroll
    for (int p = 0; p < 4; p++) {
        int idx = p * 256 + tid;
        int kr = idx >> 5, nc = (idx & 31) << 2;
        rb[p] = *(const float4*)&W[(size_t)kr * HID + n0 + nc];
    }

    for (int k0 = 0; k0 < IN; k0 += 32) {
        #pragma unroll
        for (int p = 0; p < 4; p++) {
            int idx = p * 256 + tid;
            int m = idx >> 3, k4 = (idx & 7) << 2;
            As[m][k4 + 0] = f2t(ra[p].x); As[m][k4 + 1] = f2t(ra[p].y);
            As[m][k4 + 2] = f2t(ra[p].z); As[m][k4 + 3] = f2t(ra[p].w);
        }
        #pragma unroll
        for (int p = 0; p < 4; p++) {
            int idx = p * 256 + tid;
            int kr = idx >> 5, nc = (idx & 31) << 2;
            Bs[kr][nc + 0] = f2t(rb[p].x); Bs[kr][nc + 1] = f2t(rb[p].y);
            Bs[kr][nc + 2] = f2t(rb[p].z); Bs[kr][nc + 3] = f2t(rb[p].w);
        }
        __syncthreads();

        if (k0 + 32 < IN) {
            #pragma unroll
            for (int p = 0; p < 4; p++)
                ra[p] = *(const float4*)&g_act[(size_t)a_m[p] * IN + k0 + 32 + a_k[p]];
            #pragma unroll
            for (int p = 0; p < 4; p++) {
                int idx = p * 256 + tid;
                int kr = idx >> 5, nc = (idx & 31) << 2;
                rb[p] = *(const float4*)&W[(size_t)(k0 + 32 + kr) * HID + n0 + nc];
            }
        }

        #pragma unroll
        for (int ks = 0; ks < 4; ks++) {
            const int kk = ks * 8;
            uint32_t af[4][4];
            #pragma unroll
            for (int mt = 0; mt < 4; mt++) {
                int mr = wm * 64 + mt * 16;
                af[mt][0] = As[mr + gid    ][kk + tig];
                af[mt][1] = As[mr + gid + 8][kk + tig];
                af[mt][2] = As[mr + gid    ][kk + tig + 4];
                af[mt][3] = As[mr + gid + 8][kk + tig + 4];
            }
            #pragma unroll
            for (int nt = 0; nt < 4; nt++) {
                int nb = wn * 32 + nt * 8 + gid;
                uint32_t b0 = Bs[kk + tig][nb], b1 = Bs[kk + tig + 4][nb];
                #pragma unroll
                for (int mt = 0; mt < 4; mt++)
                    mma8(acc[mt][nt][0], acc[mt][nt][1], acc[mt][nt][2], acc[mt][nt][3],
                         af[mt][0], af[mt][1], af[mt][2], af[mt][3], b0, b1);
            }
        }
        __syncthreads();
    }

    // epilogue
    #pragma unroll
    for (int mt = 0; mt < 4; mt++) {
        int lm0 = wm * 64 + mt * 16 + gid;
        int lm1 = lm0 + 8;
        int row0, row1; float w0 = 1.f, w1 = 1.f;
        if (ROUTED) {
            row0 = s_pid[lm0]; row1 = s_pid[lm1];
            w0 = s_w[lm0]; w1 = s_w[lm1];
        } else { row0 = m0 + lm0; row1 = m0 + lm1; }
        #pragma unroll
        for (int nt = 0; nt < 4; nt++) {
            int col = n0 + wn * 32 + nt * 8 + 2 * tig;
            if (row0 >= 0) {
                float2 v; v.x = w0 * acc[mt][nt][0]; v.y = w0 * acc[mt][nt][1];
                *(float2*)&Cw[(size_t)row0 * HID + col] = v;
            }
            if (row1 >= 0) {
                float2 v; v.x = w1 * acc[mt][nt][2]; v.y = w1 * acc[mt][nt][3];
                *(float2*)&Cw[(size_t)row1 * HID + col] = v;
            }
        }
    }
}

// ---------------- combine ----------------
__global__ void combine_kernel(float* __restrict__ out) {
    int v = blockIdx.x * blockDim.x + threadIdx.x;
    const int HV = HID / 4;
    if (v < TTOK * HV) {
        int t = v / HV;
        int h4 = v - t * HV;
        float4 o  = ((float4*)out)[v];
        float4 p0 = ((const float4*)g_pairout)[(size_t)(2 * t) * HV + h4];
        float4 p1 = ((const float4*)g_pairout)[(size_t)(2 * t + 1) * HV + h4];
        o.x += p0.x + p1.x; o.y += p0.y + p1.y;
        o.z += p0.z + p1.z; o.w += p0.w + p1.w;
        ((float4*)out)[v] = o;
    }
}

// ---------------- launcher ----------------
extern "C" void kernel_launch(void* const* d_in, const int* in_sizes, int n_in,
                              void* d_out, int out_size) {
    const float* x        = (const float*)d_in[0];  // [T, H]
    const float* topk_w   = (const float*)d_in[1];  // [T, 2]
    const float* W1       = (const float*)d_in[2];  // [E, H, 2I]
    const float* W2       = (const float*)d_in[3];  // [E, I, H]
    const float* Ws1      = (const float*)d_in[4];  // [H, 2SI]
    const float* Ws2      = (const float*)d_in[5];  // [SI, H]
    const int*   topk_idx = (const int*)d_in[6];    // [T, 2]
    float* out = (float*)d_out;                     // [T, H]

    (void)in_sizes; (void)n_in; (void)out_size;

    zero_cnt_kernel<<<1, 32>>>();
    route_kernel<<<NPAIR / 256, 256>>>(topk_idx, topk_w);

    // shared expert path
    gemm1_tpl<0><<<dim3(SIEXP / 64, TTOK / 128), 256>>>(x, Ws1);
    gemm2_tpl<0><<<dim3(HID / 128, TTOK / 128), 256>>>(Ws2, out);

    // routed expert path (g_act reused after shared GEMM2 consumed it)
    gemm1_tpl<1><<<dim3(IEXP / 64, NPAIR / 128, EXPERTS), 256>>>(x, W1);
    gemm2_tpl<1><<<dim3(HID / 128, NPAIR / 128, EXPERTS), 256>>>(W2, nullptr);

    combine_kernel<<<(TTOK * (HID / 4) + 255) / 256, 256>>>(out);
}

// round 7
// speedup vs baseline: 5.0792x; 1.2497x over previous
#include <cuda_runtime.h>
#include <math.h>
#include <stdint.h>

#define EXPERTS 8
#define HID     2048
#define IEXP    1408
#define SIEXP   2816
#define TTOK    4096
#define NPAIR   8192

// ---------------- scratch ----------------
__device__ int   g_cnt[EXPERTS];
__device__ int   g_tok[EXPERTS * NPAIR];
__device__ int   g_pid[EXPERTS * NPAIR];
__device__ float g_pw [EXPERTS * NPAIR];
__device__ float g_act[11534336];        // [TTOK][SIEXP] then [NPAIR][IEXP]
__device__ float g_pairout[NPAIR * HID];
// tf32-prerounded copies of inputs
__device__ float g_xr  [TTOK * HID];
__device__ float g_w1r [EXPERTS * HID * 2 * IEXP];
__device__ float g_w2r [EXPERTS * IEXP * HID];
__device__ float g_ws1r[HID * 2 * SIEXP];
__device__ float g_ws2r[SIEXP * HID];

__device__ __forceinline__ float silu_f(float a) { return a / (1.0f + expf(-a)); }

__device__ __forceinline__ uint32_t f2t(float x) {
    uint32_t r; asm("cvt.rna.tf32.f32 %0, %1;" : "=r"(r) : "f"(x)); return r;
}
__device__ __forceinline__ float f2tf(float x) { return __uint_as_float(f2t(x)); }

__device__ __forceinline__ void mma8(float& d0, float& d1, float& d2, float& d3,
                                     uint32_t a0, uint32_t a1, uint32_t a2, uint32_t a3,
                                     uint32_t b0, uint32_t b1) {
    asm volatile(
        "mma.sync.aligned.m16n8k8.row.col.f32.tf32.tf32.f32 "
        "{%0,%1,%2,%3},{%4,%5,%6,%7},{%8,%9},{%0,%1,%2,%3};"
        : "+f"(d0), "+f"(d1), "+f"(d2), "+f"(d3)
        : "r"(a0), "r"(a1), "r"(a2), "r"(a3), "r"(b0), "r"(b1));
}

__device__ __forceinline__ void cpa16(void* dst_smem, const void* src) {
    uint32_t d = (uint32_t)__cvta_generic_to_shared(dst_smem);
    asm volatile("cp.async.cg.shared.global [%0], [%1], 16;" :: "r"(d), "l"(src));
}
#define CP_COMMIT() asm volatile("cp.async.commit_group;")
#define CP_WAIT(N)  asm volatile("cp.async.wait_group %0;" :: "n"(N))

// ---------------- pre-round to tf32 ----------------
__global__ void round_tf32_kernel(const float4* __restrict__ src,
                                  float4* __restrict__ dst, int n4) {
    int i = blockIdx.x * blockDim.x + threadIdx.x;
    if (i < n4) {
        float4 v = src[i];
        v.x = f2tf(v.x); v.y = f2tf(v.y); v.z = f2tf(v.z); v.w = f2tf(v.w);
        dst[i] = v;
    }
}

// ---------------- routing ----------------
__global__ void zero_cnt_kernel() {
    if (threadIdx.x < EXPERTS) g_cnt[threadIdx.x] = 0;
}

__global__ void route_kernel(const int* __restrict__ topk_idx,
                             const float* __restrict__ topk_w) {
    int p = blockIdx.x * blockDim.x + threadIdx.x;
    if (p < NPAIR) {
        int e = topk_idx[p];
        int pos = atomicAdd(&g_cnt[e], 1);
        g_tok[e * NPAIR + pos] = p >> 1;
        g_pid[e * NPAIR + pos] = p;
        g_pw [e * NPAIR + pos] = topk_w[p];
    }
}

// =====================================================================
// GEMM1: h = silu(A @ Wg) * (A @ Wu). Inputs pre-rounded tf32.
// CTA 128x64, 8 warps = 4(M) x 2(N), warp 32x32 per half.
// Double-buffered cp.async tiles. Epilogue rounds g_act to tf32.
// dyn smem per buffer: As 128*36, Ba 32*72, Bb 32*72 (uint32) = 36864 B
// =====================================================================
#define G1_BUF (36864)
template<int ROUTED>
__global__ __launch_bounds__(256) void gemm1_tpl(const float* __restrict__ X,
                                                 const float* __restrict__ Wfull) {
    const int IN  = ROUTED ? IEXP : SIEXP;
    const int ldw = 2 * IN;
    const int m0 = blockIdx.y * 128;
    const int n0 = blockIdx.x * 64;

    extern __shared__ char dsm[];
    __shared__ int s_tok[128];
    __shared__ int s_pid[128];

    const int tid = threadIdx.x;
    const float* W = Wfull;
    if (ROUTED) {
        const int e = blockIdx.z;
        const int cnt = g_cnt[e];
        if (m0 >= cnt) return;
        W += (size_t)e * HID * ldw;
        if (tid < 128) {
            int r = m0 + tid;
            bool ok = r < cnt;
            s_tok[tid] = ok ? g_tok[e * NPAIR + r] : 0;
            s_pid[tid] = ok ? g_pid[e * NPAIR + r] : -1;
        }
        __syncthreads();
    }

    const int lane = tid & 31, w = tid >> 5;
    const int gid = lane >> 2, tig = lane & 3;
    const int wm = w & 3, wn = w >> 2;

    // per-thread cp.async coordinates
    int a_m[4];
    #pragma unroll
    for (int p = 0; p < 4; p++) {
        int m = (p * 256 + tid) >> 3;
        a_m[p] = ROUTED ? s_tok[m] : (m0 + m);
    }

    float accA[2][4][4] = {}, accB[2][4][4] = {};

    // tile issue helper (inlined via lambda-free macro style)
    #define G1_ISSUE(buf, k0)                                                        \
    {                                                                                \
        uint32_t* As = (uint32_t*)(dsm + (buf) * G1_BUF);                            \
        uint32_t* Ba = (uint32_t*)(dsm + (buf) * G1_BUF + 18432);                    \
        uint32_t* Bb = (uint32_t*)(dsm + (buf) * G1_BUF + 27648);                    \
        _Pragma("unroll")                                                            \
        for (int p = 0; p < 4; p++) {                                                \
            int idx = p * 256 + tid;                                                 \
            int m = idx >> 3, k4 = (idx & 7) << 2;                                   \
            cpa16(&As[m * 36 + k4], &X[(size_t)a_m[p] * HID + (k0) + k4]);           \
        }                                                                            \
        _Pragma("unroll")                                                            \
        for (int p = 0; p < 2; p++) {                                                \
            int idx = p * 256 + tid;                                                 \
            int kr = idx >> 4, nc = (idx & 15) << 2;                                 \
            cpa16(&Ba[kr * 72 + nc], &W[(size_t)((k0) + kr) * ldw + n0 + nc]);       \
            cpa16(&Bb[kr * 72 + nc], &W[(size_t)((k0) + kr) * ldw + IN + n0 + nc]);  \
        }                                                                            \
        CP_COMMIT();                                                                 \
    }

    G1_ISSUE(0, 0);
    int buf = 0;
    for (int k0 = 0; k0 < HID; k0 += 32) {
        const bool has_next = (k0 + 32) < HID;
        if (has_next) { G1_ISSUE(buf ^ 1, k0 + 32); CP_WAIT(1); }
        else          { CP_WAIT(0); }
        __syncthreads();

        const uint32_t* As = (const uint32_t*)(dsm + buf * G1_BUF);
        const uint32_t* Ba = (const uint32_t*)(dsm + buf * G1_BUF + 18432);
        const uint32_t* Bb = (const uint32_t*)(dsm + buf * G1_BUF + 27648);

        #pragma unroll
        for (int ks = 0; ks < 4; ks++) {
            const int kk = ks * 8;
            uint32_t af[2][4];
            #pragma unroll
            for (int mt = 0; mt < 2; mt++) {
                int mr = wm * 32 + mt * 16;
                af[mt][0] = As[(mr + gid    ) * 36 + kk + tig];
                af[mt][1] = As[(mr + gid + 8) * 36 + kk + tig];
                af[mt][2] = As[(mr + gid    ) * 36 + kk + tig + 4];
                af[mt][3] = As[(mr + gid + 8) * 36 + kk + tig + 4];
            }
            #pragma unroll
            for (int nt = 0; nt < 4; nt++) {
                int nb = wn * 32 + nt * 8 + gid;
                uint32_t ba0 = Ba[(kk + tig) * 72 + nb], ba1 = Ba[(kk + tig + 4) * 72 + nb];
                uint32_t bb0 = Bb[(kk + tig) * 72 + nb], bb1 = Bb[(kk + tig + 4) * 72 + nb];
                #pragma unroll
                for (int mt = 0; mt < 2; mt++) {
                    mma8(accA[mt][nt][0], accA[mt][nt][1], accA[mt][nt][2], accA[mt][nt][3],
                         af[mt][0], af[mt][1], af[mt][2], af[mt][3], ba0, ba1);
                    mma8(accB[mt][nt][0], accB[mt][nt][1], accB[mt][nt][2], accB[mt][nt][3],
                         af[mt][0], af[mt][1], af[mt][2], af[mt][3], bb0, bb1);
                }
            }
        }
        __syncthreads();
        buf ^= 1;
    }
    #undef G1_ISSUE

    // epilogue: swiglu (rounded to tf32 for next GEMM), write g_act
    #pragma unroll
    for (int mt = 0; mt < 2; mt++) {
        int lm0 = wm * 32 + mt * 16 + gid;
        int lm1 = lm0 + 8;
        int row0, row1;
        if (ROUTED) { row0 = s_pid[lm0]; row1 = s_pid[lm1]; }
        else        { row0 = m0 + lm0;   row1 = m0 + lm1; }
        #pragma unroll
        for (int nt = 0; nt < 4; nt++) {
            int col = n0 + wn * 32 + nt * 8 + 2 * tig;
            if (row0 >= 0) {
                float2 v;
                v.x = f2tf(silu_f(accA[mt][nt][0]) * accB[mt][nt][0]);
                v.y = f2tf(silu_f(accA[mt][nt][1]) * accB[mt][nt][1]);
                *(float2*)&g_act[(size_t)row0 * IN + col] = v;
            }
            if (row1 >= 0) {
                float2 v;
                v.x = f2tf(silu_f(accA[mt][nt][2]) * accB[mt][nt][2]);
                v.y = f2tf(silu_f(accA[mt][nt][3]) * accB[mt][nt][3]);
                *(float2*)&g_act[(size_t)row1 * IN + col] = v;
            }
        }
    }
}

// =====================================================================
// GEMM2: C = act @ W (+ optional scale, pid scatter). CTA 128x128,
// 8 warps 2(M) x 4(N), warp 64x32. Double-buffered cp.async.
// dyn smem per buffer: As 128*36, Bs 32*136 (uint32) = 35840 B
// =====================================================================
#define G2_BUF (35840)
template<int ROUTED>
__global__ __launch_bounds__(256) void gemm2_tpl(const float* __restrict__ Wfull,
                                                 float* __restrict__ C) {
    const int IN = ROUTED ? IEXP : SIEXP;   // K dim
    const int m0 = blockIdx.y * 128;
    const int n0 = blockIdx.x * 128;

    extern __shared__ char dsm[];
    __shared__ int   s_pid[128];
    __shared__ float s_w[128];

    const int tid = threadIdx.x;
    const float* W = Wfull;
    float* Cw = ROUTED ? g_pairout : C;
    if (ROUTED) {
        const int e = blockIdx.z;
        const int cnt = g_cnt[e];
        if (m0 >= cnt) return;
        W += (size_t)e * IEXP * HID;
        if (tid < 128) {
            int r = m0 + tid;
            bool ok = r < cnt;
            s_pid[tid] = ok ? g_pid[e * NPAIR + r] : -1;
            s_w[tid]   = ok ? g_pw [e * NPAIR + r] : 0.f;
        }
        __syncthreads();
    }

    const int lane = tid & 31, w = tid >> 5;
    const int gid = lane >> 2, tig = lane & 3;
    const int wm = w & 1, wn = w >> 1;

    int a_m[4];
    #pragma unroll
    for (int p = 0; p < 4; p++) {
        int m = (p * 256 + tid) >> 3;
        a_m[p] = ROUTED ? (s_pid[m] >= 0 ? s_pid[m] : 0) : (m0 + m);
    }

    float acc[4][4][4] = {};

    #define G2_ISSUE(buf, k0)                                                      \
    {                                                                              \
        uint32_t* As = (uint32_t*)(dsm + (buf) * G2_BUF);                          \
        uint32_t* Bs = (uint32_t*)(dsm + (buf) * G2_BUF + 18432);                  \
        _Pragma("unroll")                                                          \
        for (int p = 0; p < 4; p++) {                                              \
            int idx = p * 256 + tid;                                               \
            int m = idx >> 3, k4 = (idx & 7) << 2;                                 \
            cpa16(&As[m * 36 + k4], &g_act[(size_t)a_m[p] * IN + (k0) + k4]);      \
        }                                                                          \
        _Pragma("unroll")                                                          \
        for (int p = 0; p < 4; p++) {                                              \
            int idx = p * 256 + tid;                                               \
            int kr = idx >> 5, nc = (idx & 31) << 2;                               \
            cpa16(&Bs[kr * 136 + nc], &W[(size_t)((k0) + kr) * HID + n0 + nc]);    \
        }                                                                          \
        CP_COMMIT();                                                               \
    }

    G2_ISSUE(0, 0);
    int buf = 0;
    for (int k0 = 0; k0 < IN; k0 += 32) {
        const bool has_next = (k0 + 32) < IN;
        if (has_next) { G2_ISSUE(buf ^ 1, k0 + 32); CP_WAIT(1); }
        else          { CP_WAIT(0); }
        __syncthreads();

        const uint32_t* As = (const uint32_t*)(dsm + buf * G2_BUF);
        const uint32_t* Bs = (const uint32_t*)(dsm + buf * G2_BUF + 18432);

        #pragma unroll
        for (int ks = 0; ks < 4; ks++) {
            const int kk = ks * 8;
            uint32_t af[4][4];
            #pragma unroll
            for (int mt = 0; mt < 4; mt++) {
                int mr = wm * 64 + mt * 16;
                af[mt][0] = As[(mr + gid    ) * 36 + kk + tig];
                af[mt][1] = As[(mr + gid + 8) * 36 + kk + tig];
                af[mt][2] = As[(mr + gid    ) * 36 + kk + tig + 4];
                af[mt][3] = As[(mr + gid + 8) * 36 + kk + tig + 4];
            }
            #pragma unroll
            for (int nt = 0; nt < 4; nt++) {
                int nb = wn * 32 + nt * 8 + gid;
                uint32_t b0 = Bs[(kk + tig) * 136 + nb], b1 = Bs[(kk + tig + 4) * 136 + nb];
                #pragma unroll
                for (int mt = 0; mt < 4; mt++)
                    mma8(acc[mt][nt][0], acc[mt][nt][1], acc[mt][nt][2], acc[mt][nt][3],
                         af[mt][0], af[mt][1], af[mt][2], af[mt][3], b0, b1);
            }
        }
        __syncthreads();
        buf ^= 1;
    }
    #undef G2_ISSUE

    // epilogue
    #pragma unroll
    for (int mt = 0; mt < 4; mt++) {
        int lm0 = wm * 64 + mt * 16 + gid;
        int lm1 = lm0 + 8;
        int row0, row1; float w0 = 1.f, w1 = 1.f;
        if (ROUTED) {
            row0 = s_pid[lm0]; row1 = s_pid[lm1];
            w0 = s_w[lm0]; w1 = s_w[lm1];
        } else { row0 = m0 + lm0; row1 = m0 + lm1; }
        #pragma unroll
        for (int nt = 0; nt < 4; nt++) {
            int col = n0 + wn * 32 + nt * 8 + 2 * tig;
            if (row0 >= 0) {
                float2 v; v.x = w0 * acc[mt][nt][0]; v.y = w0 * acc[mt][nt][1];
                *(float2*)&Cw[(size_t)row0 * HID + col] = v;
            }
            if (row1 >= 0) {
                float2 v; v.x = w1 * acc[mt][nt][2]; v.y = w1 * acc[mt][nt][3];
                *(float2*)&Cw[(size_t)row1 * HID + col] = v;
            }
        }
    }
}

// ---------------- combine ----------------
__global__ void combine_kernel(float* __restrict__ out) {
    int v = blockIdx.x * blockDim.x + threadIdx.x;
    const int HV = HID / 4;
    if (v < TTOK * HV) {
        int t = v / HV;
        int h4 = v - t * HV;
        float4 o  = ((float4*)out)[v];
        float4 p0 = ((const float4*)g_pairout)[(size_t)(2 * t) * HV + h4];
        float4 p1 = ((const float4*)g_pairout)[(size_t)(2 * t + 1) * HV + h4];
        o.x += p0.x + p1.x; o.y += p0.y + p1.y;
        o.z += p0.z + p1.z; o.w += p0.w + p1.w;
        ((float4*)out)[v] = o;
    }
}

// ---------------- launcher ----------------
extern "C" void kernel_launch(void* const* d_in, const int* in_sizes, int n_in,
                              void* d_out, int out_size) {
    const float* x        = (const float*)d_in[0];  // [T, H]
    const float* topk_w   = (const float*)d_in[1];  // [T, 2]
    const float* W1       = (const float*)d_in[2];  // [E, H, 2I]
    const float* W2       = (const float*)d_in[3];  // [E, I, H]
    const float* Ws1      = (const float*)d_in[4];  // [H, 2SI]
    const float* Ws2      = (const float*)d_in[5];  // [SI, H]
    const int*   topk_idx = (const int*)d_in[6];    // [T, 2]
    float* out = (float*)d_out;                     // [T, H]

    (void)in_sizes; (void)n_in; (void)out_size;

    // proper device addresses of scratch symbols (R5 lesson: never &symbol from host)
    float *xr, *w1r, *w2r, *ws1r, *ws2r;
    cudaGetSymbolAddress((void**)&xr,   g_xr);
    cudaGetSymbolAddress((void**)&w1r,  g_w1r);
    cudaGetSymbolAddress((void**)&w2r,  g_w2r);
    cudaGetSymbolAddress((void**)&ws1r, g_ws1r);
    cudaGetSymbolAddress((void**)&ws2r, g_ws2r);

    // opt-in dynamic smem
    cudaFuncSetAttribute(gemm1_tpl<0>, cudaFuncAttributeMaxDynamicSharedMemorySize, 2 * G1_BUF);
    cudaFuncSetAttribute(gemm1_tpl<1>, cudaFuncAttributeMaxDynamicSharedMemorySize, 2 * G1_BUF);
    cudaFuncSetAttribute(gemm2_tpl<0>, cudaFuncAttributeMaxDynamicSharedMemorySize, 2 * G2_BUF);
    cudaFuncSetAttribute(gemm2_tpl<1>, cudaFuncAttributeMaxDynamicSharedMemorySize, 2 * G2_BUF);

    // pre-round inputs to tf32
    const int n4x   = TTOK * HID / 4;
    const int n4w1  = EXPERTS * HID * 2 * IEXP / 4;
    const int n4w2  = EXPERTS * IEXP * HID / 4;
    const int n4ws1 = HID * 2 * SIEXP / 4;
    const int n4ws2 = SIEXP * HID / 4;
    round_tf32_kernel<<<(n4x   + 255) / 256, 256>>>((const float4*)x,   (float4*)xr,   n4x);
    round_tf32_kernel<<<(n4w1  + 255) / 256, 256>>>((const float4*)W1,  (float4*)w1r,  n4w1);
    round_tf32_kernel<<<(n4w2  + 255) / 256, 256>>>((const float4*)W2,  (float4*)w2r,  n4w2);
    round_tf32_kernel<<<(n4ws1 + 255) / 256, 256>>>((const float4*)Ws1, (float4*)ws1r, n4ws1);
    round_tf32_kernel<<<(n4ws2 + 255) / 256, 256>>>((const float4*)Ws2, (float4*)ws2r, n4ws2);

    zero_cnt_kernel<<<1, 32>>>();
    route_kernel<<<NPAIR / 256, 256>>>(topk_idx, topk_w);

    // shared expert path
    gemm1_tpl<0><<<dim3(SIEXP / 64, TTOK / 128), 256, 2 * G1_BUF>>>(xr, ws1r);
    gemm2_tpl<0><<<dim3(HID / 128, TTOK / 128), 256, 2 * G2_BUF>>>(ws2r, out);

    // routed expert path (g_act reused after shared GEMM2 consumed it)
    gemm1_tpl<1><<<dim3(IEXP / 64, NPAIR / 128, EXPERTS), 256, 2 * G1_BUF>>>(xr, w1r);
    gemm2_tpl<1><<<dim3(HID / 128, NPAIR / 128, EXPERTS), 256, 2 * G2_BUF>>>(w2r, nullptr);

    combine_kernel<<<(TTOK * (HID / 4) + 255) / 256, 256>>>(out);
}

// round 10
// speedup vs baseline: 5.1133x; 1.0067x over previous
#include <cuda_runtime.h>
#include <math.h>
#include <stdint.h>

#define EXPERTS 8
#define HID     2048
#define IEXP    1408
#define SIEXP   2816
#define TTOK    4096
#define NPAIR   8192

// ---------------- scratch ----------------
__device__ int   g_cnt[EXPERTS];
__device__ int   g_tok[EXPERTS * NPAIR];
__device__ int   g_pid[EXPERTS * NPAIR];
__device__ float g_pw [EXPERTS * NPAIR];
__device__ float g_act[11534336];        // [TTOK][SIEXP] then [NPAIR][IEXP]
__device__ float g_pairout[NPAIR * HID];
// tf32-prerounded copies of inputs
__device__ float g_xr  [TTOK * HID];
__device__ float g_w1r [EXPERTS * HID * 2 * IEXP];
__device__ float g_w2r [EXPERTS * IEXP * HID];
__device__ float g_ws1r[HID * 2 * SIEXP];
__device__ float g_ws2r[SIEXP * HID];

__device__ __forceinline__ float silu_f(float a) { return a / (1.0f + expf(-a)); }

__device__ __forceinline__ uint32_t f2t(float x) {
    uint32_t r; asm("cvt.rna.tf32.f32 %0, %1;" : "=r"(r) : "f"(x)); return r;
}
__device__ __forceinline__ float f2tf(float x) { return __uint_as_float(f2t(x)); }

__device__ __forceinline__ void mma8(float& d0, float& d1, float& d2, float& d3,
                                     uint32_t a0, uint32_t a1, uint32_t a2, uint32_t a3,
                                     uint32_t b0, uint32_t b1) {
    asm volatile(
        "mma.sync.aligned.m16n8k8.row.col.f32.tf32.tf32.f32 "
        "{%0,%1,%2,%3},{%4,%5,%6,%7},{%8,%9},{%0,%1,%2,%3};"
        : "+f"(d0), "+f"(d1), "+f"(d2), "+f"(d3)
        : "r"(a0), "r"(a1), "r"(a2), "r"(a3), "r"(b0), "r"(b1));
}

__device__ __forceinline__ void cpa16(void* dst_smem, const void* src) {
    uint32_t d = (uint32_t)__cvta_generic_to_shared(dst_smem);
    asm volatile("cp.async.cg.shared.global [%0], [%1], 16;" :: "r"(d), "l"(src));
}
#define CP_COMMIT() asm volatile("cp.async.commit_group;")
#define CP_WAIT(N)  asm volatile("cp.async.wait_group %0;" :: "n"(N))

// ---------------- pre-round to tf32 ----------------
__global__ void round_tf32_kernel(const float4* __restrict__ src,
                                  float4* __restrict__ dst, int n4) {
    int i = blockIdx.x * blockDim.x + threadIdx.x;
    if (i < n4) {
        float4 v = src[i];
        v.x = f2tf(v.x); v.y = f2tf(v.y); v.z = f2tf(v.z); v.w = f2tf(v.w);
        dst[i] = v;
    }
}

// ---------------- routing ----------------
__global__ void zero_cnt_kernel() {
    if (threadIdx.x < EXPERTS) g_cnt[threadIdx.x] = 0;
}

__global__ void route_kernel(const int* __restrict__ topk_idx,
                             const float* __restrict__ topk_w) {
    int p = blockIdx.x * blockDim.x + threadIdx.x;
    if (p < NPAIR) {
        int e = topk_idx[p];
        int pos = atomicAdd(&g_cnt[e], 1);
        g_tok[e * NPAIR + pos] = p >> 1;
        g_pid[e * NPAIR + pos] = p;
        g_pw [e * NPAIR + pos] = topk_w[p];
    }
}

// =====================================================================
// GEMM1: h = silu(A @ Wg) * (A @ Wu). Inputs pre-rounded tf32.
// CTA 128x64, 8 warps = 4(M) x 2(N), warp 32x32 per half.
// 3-stage cp.async ring, ONE __syncthreads per K-step.
// buffer: As 128*36, Ba 32*72, Bb 32*72 (uint32) = 36864 B
// =====================================================================
#define G1_BUF (36864)
template<int ROUTED>
__global__ __launch_bounds__(256) void gemm1_tpl(const float* __restrict__ X,
                                                 const float* __restrict__ Wfull) {
    const int IN  = ROUTED ? IEXP : SIEXP;
    const int ldw = 2 * IN;
    const int m0 = blockIdx.y * 128;
    const int n0 = blockIdx.x * 64;

    extern __shared__ char dsm[];
    __shared__ int s_tok[128];
    __shared__ int s_pid[128];

    const int tid = threadIdx.x;
    const float* W = Wfull;
    if (ROUTED) {
        const int e = blockIdx.z;
        const int cnt = g_cnt[e];
        if (m0 >= cnt) return;
        W += (size_t)e * HID * ldw;
        if (tid < 128) {
            int r = m0 + tid;
            bool ok = r < cnt;
            s_tok[tid] = ok ? g_tok[e * NPAIR + r] : 0;
            s_pid[tid] = ok ? g_pid[e * NPAIR + r] : -1;
        }
        __syncthreads();
    }

    const int lane = tid & 31, w = tid >> 5;
    const int gid = lane >> 2, tig = lane & 3;
    const int wm = w & 3, wn = w >> 2;

    int a_m[4];
    #pragma unroll
    for (int p = 0; p < 4; p++) {
        int m = (p * 256 + tid) >> 3;
        a_m[p] = ROUTED ? s_tok[m] : (m0 + m);
    }

    float accA[2][4][4] = {}, accB[2][4][4] = {};

    #define G1_ISSUE(buf, k0)                                                        \
    {                                                                                \
        uint32_t* As = (uint32_t*)(dsm + (buf) * G1_BUF);                            \
        uint32_t* Ba = (uint32_t*)(dsm + (buf) * G1_BUF + 18432);                    \
        uint32_t* Bb = (uint32_t*)(dsm + (buf) * G1_BUF + 27648);                    \
        _Pragma("unroll")                                                            \
        for (int p = 0; p < 4; p++) {                                                \
            int idx = p * 256 + tid;                                                 \
            int m = idx >> 3, k4 = (idx & 7) << 2;                                   \
            cpa16(&As[m * 36 + k4], &X[(size_t)a_m[p] * HID + (k0) + k4]);           \
        }                                                                            \
        _Pragma("unroll")                                                            \
        for (int p = 0; p < 2; p++) {                                                \
            int idx = p * 256 + tid;                                                 \
            int kr = idx >> 4, nc = (idx & 15) << 2;                                 \
            cpa16(&Ba[kr * 72 + nc], &W[(size_t)((k0) + kr) * ldw + n0 + nc]);       \
            cpa16(&Bb[kr * 72 + nc], &W[(size_t)((k0) + kr) * ldw + IN + n0 + nc]);  \
        }                                                                            \
    }

    // preload stages 0,1
    G1_ISSUE(0, 0);  CP_COMMIT();
    G1_ISSUE(1, 32); CP_COMMIT();

    int buf = 0;
    for (int k0 = 0; k0 < HID; k0 += 32) {
        CP_WAIT(1);            // stage for this iteration is resident
        __syncthreads();       // all warps past previous compute; smem visible

        // issue stage k0+64 into buffer (buf+2)%3 (safe: last read 2 iters ago)
        int kn = k0 + 64;
        int bn = buf + 2; if (bn >= 3) bn -= 3;
        if (kn < HID) { G1_ISSUE(bn, kn); }
        CP_COMMIT();           // commit every iter (possibly empty) -> uniform wait count

        const uint32_t* As = (const uint32_t*)(dsm + buf * G1_BUF);
        const uint32_t* Ba = (const uint32_t*)(dsm + buf * G1_BUF + 18432);
        const uint32_t* Bb = (const uint32_t*)(dsm + buf * G1_BUF + 27648);

        #pragma unroll
        for (int ks = 0; ks < 4; ks++) {
            const int kk = ks * 8;
            uint32_t af[2][4];
            #pragma unroll
            for (int mt = 0; mt < 2; mt++) {
                int mr = wm * 32 + mt * 16;
                af[mt][0] = As[(mr + gid    ) * 36 + kk + tig];
                af[mt][1] = As[(mr + gid + 8) * 36 + kk + tig];
                af[mt][2] = As[(mr + gid    ) * 36 + kk + tig + 4];
                af[mt][3] = As[(mr + gid + 8) * 36 + kk + tig + 4];
            }
            #pragma unroll
            for (int nt = 0; nt < 4; nt++) {
                int nb = wn * 32 + nt * 8 + gid;
                uint32_t ba0 = Ba[(kk + tig) * 72 + nb], ba1 = Ba[(kk + tig + 4) * 72 + nb];
                uint32_t bb0 = Bb[(kk + tig) * 72 + nb], bb1 = Bb[(kk + tig + 4) * 72 + nb];
                #pragma unroll
                for (int mt = 0; mt < 2; mt++) {
                    mma8(accA[mt][nt][0], accA[mt][nt][1], accA[mt][nt][2], accA[mt][nt][3],
                         af[mt][0], af[mt][1], af[mt][2], af[mt][3], ba0, ba1);
                    mma8(accB[mt][nt][0], accB[mt][nt][1], accB[mt][nt][2], accB[mt][nt][3],
                         af[mt][0], af[mt][1], af[mt][2], af[mt][3], bb0, bb1);
                }
            }
        }
        buf = buf + 1; if (buf >= 3) buf = 0;
    }
    #undef G1_ISSUE

    // epilogue: swiglu (rounded to tf32 for next GEMM), write g_act
    #pragma unroll
    for (int mt = 0; mt < 2; mt++) {
        int lm0 = wm * 32 + mt * 16 + gid;
        int lm1 = lm0 + 8;
        int row0, row1;
        if (ROUTED) { row0 = s_pid[lm0]; row1 = s_pid[lm1]; }
        else        { row0 = m0 + lm0;   row1 = m0 + lm1; }
        #pragma unroll
        for (int nt = 0; nt < 4; nt++) {
            int col = n0 + wn * 32 + nt * 8 + 2 * tig;
            if (row0 >= 0) {
                float2 v;
                v.x = f2tf(silu_f(accA[mt][nt][0]) * accB[mt][nt][0]);
                v.y = f2tf(silu_f(accA[mt][nt][1]) * accB[mt][nt][1]);
                *(float2*)&g_act[(size_t)row0 * IN + col] = v;
            }
            if (row1 >= 0) {
                float2 v;
                v.x = f2tf(silu_f(accA[mt][nt][2]) * accB[mt][nt][2]);
                v.y = f2tf(silu_f(accA[mt][nt][3]) * accB[mt][nt][3]);
                *(float2*)&g_act[(size_t)row1 * IN + col] = v;
            }
        }
    }
}

// =====================================================================
// GEMM2: C = act @ W (+ optional scale, pid scatter). CTA 128x128,
// 8 warps 2(M) x 4(N), warp 64x32. 3-stage cp.async ring, one sync/step.
// buffer: As 128*36, Bs 32*136 (uint32) = 35840 B
// =====================================================================
#define G2_BUF (35840)
template<int ROUTED>
__global__ __launch_bounds__(256) void gemm2_tpl(const float* __restrict__ Wfull,
                                                 float* __restrict__ C) {
    const int IN = ROUTED ? IEXP : SIEXP;   // K dim
    const int m0 = blockIdx.y * 128;
    const int n0 = blockIdx.x * 128;

    extern __shared__ char dsm[];
    __shared__ int   s_pid[128];
    __shared__ float s_w[128];

    const int tid = threadIdx.x;
    const float* W = Wfull;
    float* Cw = ROUTED ? g_pairout : C;
    if (ROUTED) {
        const int e = blockIdx.z;
        const int cnt = g_cnt[e];
        if (m0 >= cnt) return;
        W += (size_t)e * IEXP * HID;
        if (tid < 128) {
            int r = m0 + tid;
            bool ok = r < cnt;
            s_pid[tid] = ok ? g_pid[e * NPAIR + r] : -1;
            s_w[tid]   = ok ? g_pw [e * NPAIR + r] : 0.f;
        }
        __syncthreads();
    }

    const int lane = tid & 31, w = tid >> 5;
    const int gid = lane >> 2, tig = lane & 3;
    const int wm = w & 1, wn = w >> 1;

    int a_m[4];
    #pragma unroll
    for (int p = 0; p < 4; p++) {
        int m = (p * 256 + tid) >> 3;
        a_m[p] = ROUTED ? (s_pid[m] >= 0 ? s_pid[m] : 0) : (m0 + m);
    }

    float acc[4][4][4] = {};

    #define G2_ISSUE(buf, k0)                                                      \
    {                                                                              \
        uint32_t* As = (uint32_t*)(dsm + (buf) * G2_BUF);                          \
        uint32_t* Bs = (uint32_t*)(dsm + (buf) * G2_BUF + 18432);                  \
        _Pragma("unroll")                                                          \
        for (int p = 0; p < 4; p++) {                                              \
            int idx = p * 256 + tid;                                               \
            int m = idx >> 3, k4 = (idx & 7) << 2;                                 \
            cpa16(&As[m * 36 + k4], &g_act[(size_t)a_m[p] * IN + (k0) + k4]);      \
        }                                                                          \
        _Pragma("unroll")                                                          \
        for (int p = 0; p < 4; p++) {                                              \
            int idx = p * 256 + tid;                                               \
            int kr = idx >> 5, nc = (idx & 31) << 2;                               \
            cpa16(&Bs[kr * 136 + nc], &W[(size_t)((k0) + kr) * HID + n0 + nc]);    \
        }                                                                          \
    }

    G2_ISSUE(0, 0);  CP_COMMIT();
    G2_ISSUE(1, 32); CP_COMMIT();

    int buf = 0;
    for (int k0 = 0; k0 < IN; k0 += 32) {
        CP_WAIT(1);
        __syncthreads();

        int kn = k0 + 64;
        int bn = buf + 2; if (bn >= 3) bn -= 3;
        if (kn < IN) { G2_ISSUE(bn, kn); }
        CP_COMMIT();

        const uint32_t* As = (const uint32_t*)(dsm + buf * G2_BUF);
        const uint32_t* Bs = (const uint32_t*)(dsm + buf * G2_BUF + 18432);

        #pragma unroll
        for (int ks = 0; ks < 4; ks++) {
            const int kk = ks * 8;
            uint32_t af[4][4];
            #pragma unroll
            for (int mt = 0; mt < 4; mt++) {
                int mr = wm * 64 + mt * 16;
                af[mt][0] = As[(mr + gid    ) * 36 + kk + tig];
                af[mt][1] = As[(mr + gid + 8) * 36 + kk + tig];
                af[mt][2] = As[(mr + gid    ) * 36 + kk + tig + 4];
                af[mt][3] = As[(mr + gid + 8) * 36 + kk + tig + 4];
            }
            #pragma unroll
            for (int nt = 0; nt < 4; nt++) {
                int nb = wn * 32 + nt * 8 + gid;
                uint32_t b0 = Bs[(kk + tig) * 136 + nb], b1 = Bs[(kk + tig + 4) * 136 + nb];
                #pragma unroll
                for (int mt = 0; mt < 4; mt++)
                    mma8(acc[mt][nt][0], acc[mt][nt][1], acc[mt][nt][2], acc[mt][nt][3],
                         af[mt][0], af[mt][1], af[mt][2], af[mt][3], b0, b1);
            }
        }
        buf = buf + 1; if (buf >= 3) buf = 0;
    }
    #undef G2_ISSUE

    // epilogue
    #pragma unroll
    for (int mt = 0; mt < 4; mt++) {
        int lm0 = wm * 64 + mt * 16 + gid;
        int lm1 = lm0 + 8;
        int row0, row1; float w0 = 1.f, w1 = 1.f;
        if (ROUTED) {
            row0 = s_pid[lm0]; row1 = s_pid[lm1];
            w0 = s_w[lm0]; w1 = s_w[lm1];
        } else { row0 = m0 + lm0; row1 = m0 + lm1; }
        #pragma unroll
        for (int nt = 0; nt < 4; nt++) {
            int col = n0 + wn * 32 + nt * 8 + 2 * tig;
            if (row0 >= 0) {
                float2 v; v.x = w0 * acc[mt][nt][0]; v.y = w0 * acc[mt][nt][1];
                *(float2*)&Cw[(size_t)row0 * HID + col] = v;
            }
            if (row1 >= 0) {
                float2 v; v.x = w1 * acc[mt][nt][2]; v.y = w1 * acc[mt][nt][3];
                *(float2*)&Cw[(size_t)row1 * HID + col] = v;
            }
        }
    }
}

// ---------------- combine ----------------
__global__ void combine_kernel(float* __restrict__ out) {
    int v = blockIdx.x * blockDim.x + threadIdx.x;
    const int HV = HID / 4;
    if (v < TTOK * HV) {
        int t = v / HV;
        int h4 = v - t * HV;
        float4 o  = ((float4*)out)[v];
        float4 p0 = ((const float4*)g_pairout)[(size_t)(2 * t) * HV + h4];
        float4 p1 = ((const float4*)g_pairout)[(size_t)(2 * t + 1) * HV + h4];
        o.x += p0.x + p1.x; o.y += p0.y + p1.y;
        o.z += p0.z + p1.z; o.w += p0.w + p1.w;
        ((float4*)out)[v] = o;
    }
}

// ---------------- launcher ----------------
extern "C" void kernel_launch(void* const* d_in, const int* in_sizes, int n_in,
                              void* d_out, int out_size) {
    const float* x        = (const float*)d_in[0];  // [T, H]
    const float* topk_w   = (const float*)d_in[1];  // [T, 2]
    const float* W1       = (const float*)d_in[2];  // [E, H, 2I]
    const float* W2       = (const float*)d_in[3];  // [E, I, H]
    const float* Ws1      = (const float*)d_in[4];  // [H, 2SI]
    const float* Ws2      = (const float*)d_in[5];  // [SI, H]
    const int*   topk_idx = (const int*)d_in[6];    // [T, 2]
    float* out = (float*)d_out;                     // [T, H]

    (void)in_sizes; (void)n_in; (void)out_size;

    float *xr, *w1r, *w2r, *ws1r, *ws2r;
    cudaGetSymbolAddress((void**)&xr,   g_xr);
    cudaGetSymbolAddress((void**)&w1r,  g_w1r);
    cudaGetSymbolAddress((void**)&w2r,  g_w2r);
    cudaGetSymbolAddress((void**)&ws1r, g_ws1r);
    cudaGetSymbolAddress((void**)&ws2r, g_ws2r);

    cudaFuncSetAttribute(gemm1_tpl<0>, cudaFuncAttributeMaxDynamicSharedMemorySize, 3 * G1_BUF);
    cudaFuncSetAttribute(gemm1_tpl<1>, cudaFuncAttributeMaxDynamicSharedMemorySize, 3 * G1_BUF);
    cudaFuncSetAttribute(gemm2_tpl<0>, cudaFuncAttributeMaxDynamicSharedMemorySize, 3 * G2_BUF);
    cudaFuncSetAttribute(gemm2_tpl<1>, cudaFuncAttributeMaxDynamicSharedMemorySize, 3 * G2_BUF);

    // pre-round inputs to tf32
    const int n4x   = TTOK * HID / 4;
    const int n4w1  = EXPERTS * HID * 2 * IEXP / 4;
    const int n4w2  = EXPERTS * IEXP * HID / 4;
    const int n4ws1 = HID * 2 * SIEXP / 4;
    const int n4ws2 = SIEXP * HID / 4;
    round_tf32_kernel<<<(n4x   + 255) / 256, 256>>>((const float4*)x,   (float4*)xr,   n4x);
    round_tf32_kernel<<<(n4w1  + 255) / 256, 256>>>((const float4*)W1,  (float4*)w1r,  n4w1);
    round_tf32_kernel<<<(n4w2  + 255) / 256, 256>>>((const float4*)W2,  (float4*)w2r,  n4w2);
    round_tf32_kernel<<<(n4ws1 + 255) / 256, 256>>>((const float4*)Ws1, (float4*)ws1r, n4ws1);
    round_tf32_kernel<<<(n4ws2 + 255) / 256, 256>>>((const float4*)Ws2, (float4*)ws2r, n4ws2);

    zero_cnt_kernel<<<1, 32>>>();
    route_kernel<<<NPAIR / 256, 256>>>(topk_idx, topk_w);

    // shared expert path
    gemm1_tpl<0><<<dim3(SIEXP / 64, TTOK / 128), 256, 3 * G1_BUF>>>(xr, ws1r);
    gemm2_tpl<0><<<dim3(HID / 128, TTOK / 128), 256, 3 * G2_BUF>>>(ws2r, out);

    // routed expert path (g_act reused after shared GEMM2 consumed it)
    gemm1_tpl<1><<<dim3(IEXP / 64, NPAIR / 128, EXPERTS), 256, 3 * G1_BUF>>>(xr, w1r);
    gemm2_tpl<1><<<dim3(HID / 128, NPAIR / 128, EXPERTS), 256, 3 * G2_BUF>>>(w2r, nullptr);

    combine_kernel<<<(TTOK * (HID / 4) + 255) / 256, 256>>>(out);
}